// round 11
// baseline (speedup 1.0000x reference)
#include <cuda_runtime.h>
#include <cuda_fp16.h>
#include <cstdint>
#include <cstddef>
#include <cstring>

#define NM 16384
#define ND 2048
#define NE 64
#define TM 512
#define KC 32
#define NSPLIT 4
#define KQ (ND/NSPLIT)      // 512 k per CTA
#define NSTG (KQ/KC)        // 16 stages

#define XROWB 144           // 36-float padded row: conflict-free LDS.64
#define XBUF_SZ (TM*XROWB)  // 73728 per stage
#define WOFF (2*XBUF_SZ)    // 147456
#define WSTG 8192           // 64 experts x 128B (hi|lo packed)
#define SMEM_BYTES (WOFF + 2*WSTG)  // 163840 -> 1 CTA/SM

#define SW128(o) ((o) ^ (((o) >> 3) & 0x70))

__device__ __align__(16) __half g_Whi[NE * ND];
__device__ __align__(16) __half g_Wlo[NE * ND];
__device__ __align__(16) float  g_part[NSPLIT][NM][NE];   // 16 MB partials

// ---------- helpers ----------
__device__ __forceinline__ uint32_t smem_u32(const void* p) {
    uint32_t a;
    asm("{ .reg .u64 t; cvta.to.shared.u64 t, %1; cvt.u32.u64 %0, t; }" : "=r"(a) : "l"(p));
    return a;
}
__device__ __forceinline__ void cpa16(uint32_t dst, const void* src) {
    uint64_t g = __cvta_generic_to_global((void*)src);
    asm volatile("cp.async.cg.shared.global [%0], [%1], 16;" :: "r"(dst), "l"(g) : "memory");
}
__device__ __forceinline__ void cpa_commit() {
    asm volatile("cp.async.commit_group;" ::: "memory");
}
__device__ __forceinline__ void cpa_wait1() {
    asm volatile("cp.async.wait_group 1;" ::: "memory");
}
__device__ __forceinline__ void ldm4(uint32_t* r, uint32_t addr) {
    asm volatile("ldmatrix.sync.aligned.m8n8.x4.shared.b16 {%0,%1,%2,%3}, [%4];"
                 : "=r"(r[0]), "=r"(r[1]), "=r"(r[2]), "=r"(r[3]) : "r"(addr));
}
__device__ __forceinline__ void mma16816(float* d, const uint32_t* a, uint32_t b0, uint32_t b1) {
    asm volatile(
        "mma.sync.aligned.m16n8k16.row.col.f32.f16.f16.f32 "
        "{%0,%1,%2,%3}, {%4,%5,%6,%7}, {%8,%9}, {%0,%1,%2,%3};"
        : "+f"(d[0]), "+f"(d[1]), "+f"(d[2]), "+f"(d[3])
        : "r"(a[0]), "r"(a[1]), "r"(a[2]), "r"(a[3]), "r"(b0), "r"(b1));
}
__device__ __forceinline__ void split2(float2 v, uint32_t& hi, uint32_t& lo) {
    __half2 h = __floats2half2_rn(v.x, v.y);
    float2 hf = __half22float2(h);
    __half2 l = __floats2half2_rn(v.x - hf.x, v.y - hf.y);
    memcpy(&hi, &h, 4); memcpy(&lo, &l, 4);
}

// ---------- W prep: 16 k-rows per block (grid 128), coalesced both sides ----------
__global__ __launch_bounds__(256)
void prep_W(const float* __restrict__ W) {
    __shared__ float t[16][65];
    const int tid = threadIdx.x;
    const int kb = blockIdx.x * 16;
    {
        const int r = tid >> 4, c4 = (tid & 15) * 4;
        float4 v = *(const float4*)&W[(size_t)(kb + r) * NE + c4];
        t[r][c4] = v.x; t[r][c4 + 1] = v.y; t[r][c4 + 2] = v.z; t[r][c4 + 3] = v.w;
    }
    __syncthreads();
    const int e = tid >> 2, kc = tid & 3;        // 4 consecutive k per thread
    __half hi[4], lo[4];
    #pragma unroll
    for (int j = 0; j < 4; j++) {
        const float v = t[kc * 4 + j][e];
        const __half h = __float2half_rn(v);
        hi[j] = h;
        lo[j] = __float2half_rn(v - __half2float(h));
    }
    uint2 uh, ul;
    memcpy(&uh, hi, 8); memcpy(&ul, lo, 8);
    const size_t off = (size_t)e * ND + kb + kc * 4;
    *(uint2*)&g_Whi[off] = uh;
    *(uint2*)&g_Wlo[off] = ul;
}

// ---------- GEMM: 512-token x quarter-K per CTA, warp tile m64 ----------
__global__ __launch_bounds__(256, 1)
void router_mma(const float* __restrict__ x)
{
    extern __shared__ __align__(1024) char smem[];
    const uint32_t sb = smem_u32(smem);

    const int tid = threadIdx.x, wid = tid >> 5, lane = tid & 31;
    const int gid = lane >> 2, t = lane & 3;
    const int m0 = blockIdx.x * TM;
    const int z  = blockIdx.y;
    const int kbase = z * KQ;

    const int q = lane >> 3, lr = lane & 7;
    const uint32_t b_base = (uint32_t)((((q >> 1) * 8) + lr) * 128 + (q & 1) * 16);

    // acc[sub][nf][4]: sub = m16 slice (0..3), nf = n8 frag (0..7)
    float acc[4][8][4];
    #pragma unroll
    for (int s0 = 0; s0 < 4; s0++)
        #pragma unroll
        for (int i = 0; i < 8; i++)
            #pragma unroll
            for (int j = 0; j < 4; j++) acc[s0][i][j] = 0.0f;

    const int we = tid >> 2, wj = tid & 3;   // W loader: expert, 16B chunk

    auto issue = [&](int s) {
        if (s < NSTG) {
            const uint32_t xb = sb + (s & 1) * XBUF_SZ;
            const int k0 = kbase + s * KC;
            #pragma unroll
            for (int i = 0; i < 16; i++) {
                const int id = tid + 256 * i;
                const int row = id >> 3, c = id & 7;
                cpa16(xb + row * XROWB + c * 16,
                      &x[(size_t)(m0 + row) * ND + k0 + c * 4]);
            }
            const uint32_t wb = sb + WOFF + (s & 1) * WSTG;
            cpa16(wb + SW128((uint32_t)(we * 128 + wj * 16)),
                  &g_Whi[(size_t)we * ND + k0 + wj * 8]);
            cpa16(wb + SW128((uint32_t)(we * 128 + 64 + wj * 16)),
                  &g_Wlo[(size_t)we * ND + k0 + wj * 8]);
        }
        cpa_commit();
    };

    issue(0);
    for (int s = 0; s < NSTG; s++) {
        issue(s + 1);
        cpa_wait1();
        __syncthreads();

        const char* xp = smem + (s & 1) * XBUF_SZ;
        const uint32_t wb = sb + WOFF + (s & 1) * WSTG;

        #pragma unroll
        for (int kc = 0; kc < 2; kc++) {
            #pragma unroll
            for (int nb = 0; nb < 4; nb++) {
                uint32_t bh[4], bl[4];
                const uint32_t bo = b_base + nb * 2048 + kc * 32;
                ldm4(bh, wb + SW128(bo));
                ldm4(bl, wb + SW128(bo + 64));
                #pragma unroll
                for (int sub = 0; sub < 4; sub++) {
                    const int row = wid * 64 + sub * 16 + gid;
                    const char* rp = xp + row * XROWB + (kc * 16 + 2 * t) * 4;
                    float2 a0 = *(const float2*)(rp);
                    float2 a1 = *(const float2*)(rp + 8 * XROWB);
                    float2 a2 = *(const float2*)(rp + 32);
                    float2 a3 = *(const float2*)(rp + 8 * XROWB + 32);
                    uint32_t ah[4], al[4];
                    split2(a0, ah[0], al[0]);
                    split2(a1, ah[1], al[1]);
                    split2(a2, ah[2], al[2]);
                    split2(a3, ah[3], al[3]);
                    float* p0 = acc[sub][2 * nb];
                    float* p1 = acc[sub][2 * nb + 1];
                    mma16816(p0, ah, bh[0], bh[1]);
                    mma16816(p0, ah, bl[0], bl[1]);
                    mma16816(p0, al, bh[0], bh[1]);
                    mma16816(p1, ah, bh[2], bh[3]);
                    mma16816(p1, ah, bl[2], bl[3]);
                    mma16816(p1, al, bh[2], bh[3]);
                }
            }
        }
        __syncthreads();
    }

    // ---- write fp32 partials ----
    #pragma unroll
    for (int sub = 0; sub < 4; sub++) {
        const int token = m0 + wid * 64 + sub * 16 + gid;
        #pragma unroll
        for (int nf = 0; nf < 8; nf++) {
            const int e0 = nf * 8 + 2 * t;
            float* p = &g_part[z][token][e0];
            *(float2*)p            = make_float2(acc[sub][nf][0], acc[sub][nf][1]);
            *(float2*)(p + 8 * NE) = make_float2(acc[sub][nf][2], acc[sub][nf][3]);
        }
    }
}

// ---------- combine 4 partial slices + bias + noise + softmax + top-2 ----------
__global__ __launch_bounds__(256)
void combine(const float* __restrict__ bias, const float* __restrict__ noise,
             float* __restrict__ out)
{
    __shared__ float lg[128 * 68];
    const int tid = threadIdx.x;
    const int t0 = blockIdx.x * 128;

    #pragma unroll
    for (int i = 0; i < 8; i++) {
        const int id = tid + 256 * i;
        const int off = id * 4;
        const int row = off >> 6, col = off & 63;
        float4 a = *(const float4*)(&g_part[0][t0][0] + off);
        float4 b = *(const float4*)(&g_part[1][t0][0] + off);
        float4 c = *(const float4*)(&g_part[2][t0][0] + off);
        float4 d = *(const float4*)(&g_part[3][t0][0] + off);
        a.x += b.x + c.x + d.x;
        a.y += b.y + c.y + d.y;
        a.z += b.z + c.z + d.z;
        a.w += b.w + c.w + d.w;
        *(float4*)&lg[row * 68 + col] = a;
    }
    __syncthreads();

    if (tid < 128) {
        const int token = t0 + tid;
        float* row = &lg[tid * 68];

        float mx = -3.0e38f;
        #pragma unroll
        for (int j = 0; j < NE / 4; j++) {
            float4 v  = *(float4*)&row[4 * j];
            float4 nz = *(const float4*)&noise[(size_t)token * NE + 4 * j];
            float4 bb = *(const float4*)&bias[4 * j];
            v.x += bb.x + 0.1f * nz.x;
            v.y += bb.y + 0.1f * nz.y;
            v.z += bb.z + 0.1f * nz.z;
            v.w += bb.w + 0.1f * nz.w;
            mx = fmaxf(mx, fmaxf(fmaxf(v.x, v.y), fmaxf(v.z, v.w)));
            *(float4*)&row[4 * j] = v;
        }
        float sum = 0.0f;
        #pragma unroll
        for (int j = 0; j < NE / 4; j++) {
            float4 v = *(float4*)&row[4 * j];
            v.x = expf(v.x - mx);
            v.y = expf(v.y - mx);
            v.z = expf(v.z - mx);
            v.w = expf(v.w - mx);
            sum += (v.x + v.y) + (v.z + v.w);
            *(float4*)&row[4 * j] = v;
        }
        const float inv = 1.0f / sum;

        float m1 = -1.0f, m2 = -1.0f;
        int i1 = 0, i2 = 0;
        float* out_sc = out + (size_t)NM * 4;
        #pragma unroll
        for (int j = 0; j < NE / 4; j++) {
            float4 v = *(float4*)&row[4 * j];
            v.x *= inv; v.y *= inv; v.z *= inv; v.w *= inv;
            *(float4*)&out_sc[(size_t)token * NE + 4 * j] = v;
            float vs[4] = {v.x, v.y, v.z, v.w};
            #pragma unroll
            for (int l = 0; l < 4; l++) {
                const int idx = 4 * j + l;
                const float val = vs[l];
                if (val > m1)      { m2 = m1; i2 = i1; m1 = val; i1 = idx; }
                else if (val > m2) { m2 = val; i2 = idx; }
            }
        }
        out[(size_t)token * 2 + 0] = m1;
        out[(size_t)token * 2 + 1] = m2;
        out[(size_t)NM * 2 + (size_t)token * 2 + 0] = (float)i1;
        out[(size_t)NM * 2 + (size_t)token * 2 + 1] = (float)i2;
    }
}

extern "C" void kernel_launch(void* const* d_in, const int* in_sizes, int n_in,
                              void* d_out, int out_size) {
    const float* x     = (const float*)d_in[0];
    const float* W     = (const float*)d_in[1];
    const float* b     = (const float*)d_in[2];
    const float* noise = (const float*)d_in[3];

    cudaFuncSetAttribute(router_mma, cudaFuncAttributeMaxDynamicSharedMemorySize, SMEM_BYTES);

    prep_W<<<ND / 16, 256>>>(W);
    router_mma<<<dim3(NM / TM, NSPLIT, 1), 256, SMEM_BYTES>>>(x);
    combine<<<NM / 128, 256>>>(b, noise, (float*)d_out);
}

// round 12
// speedup vs baseline: 1.0412x; 1.0412x over previous
#include <cuda_runtime.h>
#include <cuda_fp16.h>
#include <cstdint>
#include <cstddef>
#include <cstring>

#define NM 16384
#define ND 2048
#define NE 64
#define TM 256
#define KC 64
#define NSPLIT 2
#define KQ (ND/NSPLIT)      // 1024 k per CTA
#define NSTG (KQ/KC)        // 16 stages
#define NTHR 512

#define XROWB 272           // 68-float padded row (same bank residue as proven 144)
#define XBUF_SZ (TM*XROWB)  // 69632 per stage
#define WOFF (2*XBUF_SZ)    // 139264
#define WSTG 16384          // hi 8K + lo 8K
#define SMEM_BYTES (WOFF + 2*WSTG)  // 172032 -> 1 CTA/SM

#define SW128(o) ((o) ^ (((o) >> 3) & 0x70))

__device__ __align__(16) __half g_Whi[NE * ND];
__device__ __align__(16) __half g_Wlo[NE * ND];
__device__ __align__(16) float  g_part[NSPLIT][NM][NE];   // 8 MB partials

// ---------- helpers ----------
__device__ __forceinline__ uint32_t smem_u32(const void* p) {
    uint32_t a;
    asm("{ .reg .u64 t; cvta.to.shared.u64 t, %1; cvt.u32.u64 %0, t; }" : "=r"(a) : "l"(p));
    return a;
}
__device__ __forceinline__ void cpa16(uint32_t dst, const void* src) {
    uint64_t g = __cvta_generic_to_global((void*)src);
    asm volatile("cp.async.cg.shared.global [%0], [%1], 16;" :: "r"(dst), "l"(g) : "memory");
}
__device__ __forceinline__ void cpa_commit() {
    asm volatile("cp.async.commit_group;" ::: "memory");
}
__device__ __forceinline__ void cpa_wait1() {
    asm volatile("cp.async.wait_group 1;" ::: "memory");
}
__device__ __forceinline__ void ldm4(uint32_t* r, uint32_t addr) {
    asm volatile("ldmatrix.sync.aligned.m8n8.x4.shared.b16 {%0,%1,%2,%3}, [%4];"
                 : "=r"(r[0]), "=r"(r[1]), "=r"(r[2]), "=r"(r[3]) : "r"(addr));
}
__device__ __forceinline__ void mma16816(float* d, const uint32_t* a, uint32_t b0, uint32_t b1) {
    asm volatile(
        "mma.sync.aligned.m16n8k16.row.col.f32.f16.f16.f32 "
        "{%0,%1,%2,%3}, {%4,%5,%6,%7}, {%8,%9}, {%0,%1,%2,%3};"
        : "+f"(d[0]), "+f"(d[1]), "+f"(d[2]), "+f"(d[3])
        : "r"(a[0]), "r"(a[1]), "r"(a[2]), "r"(a[3]), "r"(b0), "r"(b1));
}
__device__ __forceinline__ void split2(float2 v, uint32_t& hi, uint32_t& lo) {
    __half2 h = __floats2half2_rn(v.x, v.y);
    float2 hf = __half22float2(h);
    __half2 l = __floats2half2_rn(v.x - hf.x, v.y - hf.y);
    memcpy(&hi, &h, 4); memcpy(&lo, &l, 4);
}

// ---------- W prep: 16 k-rows per block (grid 128), coalesced both sides ----------
__global__ __launch_bounds__(256)
void prep_W(const float* __restrict__ W) {
    __shared__ float t[16][65];
    const int tid = threadIdx.x;
    const int kb = blockIdx.x * 16;
    {
        const int r = tid >> 4, c4 = (tid & 15) * 4;
        float4 v = *(const float4*)&W[(size_t)(kb + r) * NE + c4];
        t[r][c4] = v.x; t[r][c4 + 1] = v.y; t[r][c4 + 2] = v.z; t[r][c4 + 3] = v.w;
    }
    __syncthreads();
    const int e = tid >> 2, kc = tid & 3;
    __half hi[4], lo[4];
    #pragma unroll
    for (int j = 0; j < 4; j++) {
        const float v = t[kc * 4 + j][e];
        const __half h = __float2half_rn(v);
        hi[j] = h;
        lo[j] = __float2half_rn(v - __half2float(h));
    }
    uint2 uh, ul;
    memcpy(&uh, hi, 8); memcpy(&ul, lo, 8);
    const size_t off = (size_t)e * ND + kb + kc * 4;
    *(uint2*)&g_Whi[off] = uh;
    *(uint2*)&g_Wlo[off] = ul;
}

// ---------- GEMM: 256-token x half-K per CTA, 512 threads, 16 warps x m16 ----------
__global__ __launch_bounds__(NTHR, 1)
void router_mma(const float* __restrict__ x)
{
    extern __shared__ __align__(1024) char smem[];
    const uint32_t sb = smem_u32(smem);

    const int tid = threadIdx.x, wid = tid >> 5, lane = tid & 31;
    const int gid = lane >> 2, t = lane & 3;
    const int m0 = blockIdx.x * TM;
    const int z  = blockIdx.y;
    const int kbase = z * KQ;
    const int wrow = wid * 16;          // warp's 16-token slice

    const int q = lane >> 3, lr = lane & 7;
    const uint32_t b_base = (uint32_t)((((q >> 1) * 8) + lr) * 128 + (q & 1) * 16);

    float acc[8][4];
    #pragma unroll
    for (int i = 0; i < 8; i++)
        #pragma unroll
        for (int j = 0; j < 4; j++) acc[i][j] = 0.0f;

    const int we = tid >> 3, wj = tid & 7;   // W loader: expert, 16B chunk (512 thr -> 1 each)

    auto issue = [&](int s) {
        if (s < NSTG) {
            const uint32_t xb = sb + (s & 1) * XBUF_SZ;
            const int k0 = kbase + s * KC;
            #pragma unroll
            for (int i = 0; i < 8; i++) {
                const int id = tid + NTHR * i;
                const int row = id >> 4, c = id & 15;
                cpa16(xb + row * XROWB + c * 16,
                      &x[(size_t)(m0 + row) * ND + k0 + c * 4]);
            }
            const uint32_t wb = sb + WOFF + (s & 1) * WSTG;
            const uint32_t so = SW128((uint32_t)(we * 128 + wj * 16));
            cpa16(wb + so,        &g_Whi[(size_t)we * ND + k0 + wj * 8]);
            cpa16(wb + 8192 + so, &g_Wlo[(size_t)we * ND + k0 + wj * 8]);
        }
        cpa_commit();
    };

    issue(0);
    for (int s = 0; s < NSTG; s++) {
        issue(s + 1);
        cpa_wait1();
        __syncthreads();

        const char* xp = smem + (s & 1) * XBUF_SZ;
        const uint32_t wh = sb + WOFF + (s & 1) * WSTG, wlo = wh + 8192;

        #pragma unroll
        for (int kc = 0; kc < 4; kc++) {
            // A: load + split once per kc (hoisted out of nb loop)
            const char* rp = xp + (wrow + gid) * XROWB + (kc * 16 + 2 * t) * 4;
            float2 a0 = *(const float2*)(rp);
            float2 a1 = *(const float2*)(rp + 8 * XROWB);
            float2 a2 = *(const float2*)(rp + 32);
            float2 a3 = *(const float2*)(rp + 8 * XROWB + 32);
            uint32_t ah[4], al[4];
            split2(a0, ah[0], al[0]);
            split2(a1, ah[1], al[1]);
            split2(a2, ah[2], al[2]);
            split2(a3, ah[3], al[3]);

            const uint32_t bo0 = b_base + kc * 32;
            #pragma unroll
            for (int nb = 0; nb < 4; nb++) {
                uint32_t bh[4], bl[4];
                const uint32_t bo = SW128(bo0 + nb * 2048);
                ldm4(bh, wh  + bo);
                ldm4(bl, wlo + bo);
                float* p0 = acc[2 * nb];
                float* p1 = acc[2 * nb + 1];
                mma16816(p0, ah, bh[0], bh[1]);
                mma16816(p0, ah, bl[0], bl[1]);
                mma16816(p0, al, bh[0], bh[1]);
                mma16816(p1, ah, bh[2], bh[3]);
                mma16816(p1, ah, bl[2], bl[3]);
                mma16816(p1, al, bh[2], bh[3]);
            }
        }
        __syncthreads();
    }

    // ---- write fp32 partials ----
    {
        const int token = m0 + wrow + gid;
        #pragma unroll
        for (int nf = 0; nf < 8; nf++) {
            const int e0 = nf * 8 + 2 * t;
            float* p = &g_part[z][token][e0];
            *(float2*)p            = make_float2(acc[nf][0], acc[nf][1]);
            *(float2*)(p + 8 * NE) = make_float2(acc[nf][2], acc[nf][3]);
        }
    }
}

// ---------- combine 2 partial slices + bias + noise + softmax + top-2 ----------
__global__ __launch_bounds__(256)
void combine(const float* __restrict__ bias, const float* __restrict__ noise,
             float* __restrict__ out)
{
    __shared__ float lg[128 * 68];
    const int tid = threadIdx.x;
    const int t0 = blockIdx.x * 128;

    #pragma unroll
    for (int i = 0; i < 8; i++) {
        const int id = tid + 256 * i;
        const int off = id * 4;
        const int row = off >> 6, col = off & 63;
        float4 a = *(const float4*)(&g_part[0][t0][0] + off);
        float4 b = *(const float4*)(&g_part[1][t0][0] + off);
        a.x += b.x; a.y += b.y; a.z += b.z; a.w += b.w;
        *(float4*)&lg[row * 68 + col] = a;
    }
    __syncthreads();

    if (tid < 128) {
        const int token = t0 + tid;
        float* row = &lg[tid * 68];

        float mx = -3.0e38f;
        #pragma unroll
        for (int j = 0; j < NE / 4; j++) {
            float4 v  = *(float4*)&row[4 * j];
            float4 nz = *(const float4*)&noise[(size_t)token * NE + 4 * j];
            float4 bb = *(const float4*)&bias[4 * j];
            v.x += bb.x + 0.1f * nz.x;
            v.y += bb.y + 0.1f * nz.y;
            v.z += bb.z + 0.1f * nz.z;
            v.w += bb.w + 0.1f * nz.w;
            mx = fmaxf(mx, fmaxf(fmaxf(v.x, v.y), fmaxf(v.z, v.w)));
            *(float4*)&row[4 * j] = v;
        }
        float sum = 0.0f;
        #pragma unroll
        for (int j = 0; j < NE / 4; j++) {
            float4 v = *(float4*)&row[4 * j];
            v.x = expf(v.x - mx);
            v.y = expf(v.y - mx);
            v.z = expf(v.z - mx);
            v.w = expf(v.w - mx);
            sum += (v.x + v.y) + (v.z + v.w);
            *(float4*)&row[4 * j] = v;
        }
        const float inv = 1.0f / sum;

        float m1 = -1.0f, m2 = -1.0f;
        int i1 = 0, i2 = 0;
        float* out_sc = out + (size_t)NM * 4;
        #pragma unroll
        for (int j = 0; j < NE / 4; j++) {
            float4 v = *(float4*)&row[4 * j];
            v.x *= inv; v.y *= inv; v.z *= inv; v.w *= inv;
            *(float4*)&out_sc[(size_t)token * NE + 4 * j] = v;
            float vs[4] = {v.x, v.y, v.z, v.w};
            #pragma unroll
            for (int l = 0; l < 4; l++) {
                const int idx = 4 * j + l;
                const float val = vs[l];
                if (val > m1)      { m2 = m1; i2 = i1; m1 = val; i1 = idx; }
                else if (val > m2) { m2 = val; i2 = idx; }
            }
        }
        out[(size_t)token * 2 + 0] = m1;
        out[(size_t)token * 2 + 1] = m2;
        out[(size_t)NM * 2 + (size_t)token * 2 + 0] = (float)i1;
        out[(size_t)NM * 2 + (size_t)token * 2 + 1] = (float)i2;
    }
}

extern "C" void kernel_launch(void* const* d_in, const int* in_sizes, int n_in,
                              void* d_out, int out_size) {
    const float* x     = (const float*)d_in[0];
    const float* W     = (const float*)d_in[1];
    const float* b     = (const float*)d_in[2];
    const float* noise = (const float*)d_in[3];

    cudaFuncSetAttribute(router_mma, cudaFuncAttributeMaxDynamicSharedMemorySize, SMEM_BYTES);

    prep_W<<<ND / 16, 256>>>(W);
    router_mma<<<dim3(NM / TM, NSPLIT, 1), NTHR, SMEM_BYTES>>>(x);
    combine<<<NM / 128, 256>>>(b, noise, (float*)d_out);
}